// round 1
// baseline (speedup 1.0000x reference)
#include <cuda_runtime.h>
#include <math.h>

#define NB 1024
#define DM 1024
#define DH 64
#define NH 16
#define NA 4
#define NSLOT (NB*NA)

// ---------------- scratch (__device__ globals; no allocation allowed) --------
__device__ int           g_counts[NH];
__device__ int           g_list[NH*NB];        // packed (b<<2)|a  == slot id
__device__ unsigned char g_mask[NB*NH];        // 1 if slot (b,h) selected
__device__ int           g_topi[NSLOT];
__device__ float         g_topp[NSLOT];
__device__ float         g_toplg[NSLOT];
__device__ float         g_qb[NSLOT*DH];
__device__ float         g_kb[NSLOT*DH];
__device__ float         g_vb[NSLOT*DH];
__device__ float         g_outp[NSLOT*DH];     // out * top_p
__device__ float         g_scr[NSLOT*DM];      // merged contributions (16MB)

// ---------------- K0: zero counts + mask ------------------------------------
__global__ void k_zero() {
    int i = blockIdx.x * 256 + threadIdx.x;
    if (i < NH) g_counts[i] = 0;
    if (i < NB*NH) g_mask[i] = 0;
}

// ---------------- K1: routing (logits, softmax, top-4, head lists) ----------
__global__ __launch_bounds__(128) void k_route(const float* __restrict__ query,
                                               const float* __restrict__ We,
                                               const float* __restrict__ be) {
    __shared__ float qs[DM];
    __shared__ float lg[NH];
    int b = blockIdx.x;
    int tid = threadIdx.x;
    for (int i = tid; i < DM; i += 128) qs[i] = query[b*DM + i];
    __syncthreads();
    int w = tid >> 5, lane = tid & 31;
    #pragma unroll
    for (int hh = 0; hh < 4; hh++) {
        int h = w*4 + hh;
        const float* wr = We + h*DM;
        float s = 0.f;
        for (int m = lane; m < DM; m += 32) s += qs[m] * wr[m];
        #pragma unroll
        for (int o = 16; o > 0; o >>= 1) s += __shfl_xor_sync(0xffffffffu, s, o);
        if (lane == 0) lg[h] = s + be[h];
    }
    __syncthreads();
    if (tid == 0) {
        float l[NH], p[NH];
        float mx = -1e30f;
        #pragma unroll
        for (int h = 0; h < NH; h++) { l[h] = lg[h]; mx = fmaxf(mx, l[h]); }
        float se = 0.f;
        #pragma unroll
        for (int h = 0; h < NH; h++) { p[h] = expf(l[h] - mx); se += p[h]; }
        float inv = 1.f / se;
        #pragma unroll
        for (int h = 0; h < NH; h++) p[h] *= inv;
        bool used[NH];
        #pragma unroll
        for (int h = 0; h < NH; h++) used[h] = false;
        for (int a = 0; a < NA; a++) {
            int bi = -1; float bp = -1.f;
            for (int h = 0; h < NH; h++)
                if (!used[h] && p[h] > bp) { bp = p[h]; bi = h; }   // ties -> lowest idx
            used[bi] = true;
            int slot = b*NA + a;
            g_topi[slot]  = bi;
            g_topp[slot]  = bp;
            g_toplg[slot] = l[bi];
            g_mask[b*NH + bi] = 1;
            int pos = atomicAdd(&g_counts[bi], 1);
            g_list[bi*NB + pos] = (b << 2) | a;   // packed == slot id
        }
    }
}

// ---------------- K2: head-grouped QKV projections ---------------------------
// grid (32 chunks, 16 heads), 128 threads. Tile: 32 tokens x 64 out, K=1024.
__global__ __launch_bounds__(128) void k_proj(
    const float* __restrict__ query, const float* __restrict__ key,
    const float* __restrict__ value,
    const float* __restrict__ Wq, const float* __restrict__ bq,
    const float* __restrict__ Wk, const float* __restrict__ bk,
    const float* __restrict__ Wv, const float* __restrict__ bv)
{
    int h  = blockIdx.y;
    int n0 = blockIdx.x * 32;
    int cnt = g_counts[h];
    if (n0 >= cnt) return;

    __shared__ float Xs[32*65];
    __shared__ float Ws[64*65];
    __shared__ int   ent_s[32];

    int tid = threadIdx.x;
    if (tid < 32) {
        int idx = n0 + tid;
        ent_s[tid] = g_list[h*NB + (idx < cnt ? idx : n0)];
    }
    __syncthreads();

    int tx = tid & 15, ty = tid >> 4;   // tx: 16 d-groups, ty: 8 t-groups

    const float* Xp[3] = {query, key, value};
    const float* Wp[3] = {Wq, Wk, Wv};
    const float* Bp[3] = {bq, bk, bv};
    float*       Op[3] = {g_qb, g_kb, g_vb};

    for (int mm = 0; mm < 3; mm++) {
        const float* X = Xp[mm];
        const float* W = Wp[mm] + (size_t)h*DH*DM;
        float acc[4][4];
        #pragma unroll
        for (int i = 0; i < 4; i++)
            #pragma unroll
            for (int j = 0; j < 4; j++) acc[i][j] = 0.f;

        for (int kt = 0; kt < DM; kt += 64) {
            #pragma unroll
            for (int idx = tid; idx < 32*64; idx += 128) {
                int t = idx >> 6, kk = idx & 63;
                Xs[t*65 + kk] = X[(ent_s[t] >> 2)*DM + kt + kk];
            }
            #pragma unroll
            for (int idx = tid; idx < 64*64; idx += 128) {
                int d = idx >> 6, kk = idx & 63;
                Ws[kk*65 + d] = W[d*DM + kt + kk];    // transposed store, stride 65: CF
            }
            __syncthreads();
            #pragma unroll 8
            for (int kk = 0; kk < 64; kk++) {
                float xv[4], wv[4];
                #pragma unroll
                for (int i = 0; i < 4; i++) xv[i] = Xs[(ty + 8*i)*65 + kk];
                #pragma unroll
                for (int j = 0; j < 4; j++) wv[j] = Ws[kk*65 + tx + 16*j];
                #pragma unroll
                for (int i = 0; i < 4; i++)
                    #pragma unroll
                    for (int j = 0; j < 4; j++) acc[i][j] += xv[i]*wv[j];
            }
            __syncthreads();
        }
        float* O = Op[mm];
        #pragma unroll
        for (int i = 0; i < 4; i++) {
            int t = ty + 8*i;
            if (n0 + t < cnt) {
                int slot = ent_s[t];
                #pragma unroll
                for (int j = 0; j < 4; j++) {
                    int d = tx + 16*j;
                    O[slot*DH + d] = acc[i][j] + Bp[mm][h*DH + d];
                }
            }
        }
    }
}

// ---------------- K3: per-slot attention update + state write ---------------
// grid NSLOT blocks, 64 threads (thread = column e).
__global__ __launch_bounds__(64) void k_slot(
    const float* __restrict__ matrix, const float* __restrict__ normalizer,
    const float* __restrict__ Ww, const float* __restrict__ bw,
    const float* __restrict__ dlg,
    float* __restrict__ out_matrix, float* __restrict__ out_norm)
{
    __shared__ float Ssm[64*64];
    __shared__ float phiq_s[64], phik_s[64], dec_s[64];
    __shared__ float partial[6];

    int slot = blockIdx.x;
    int e = threadIdx.x;
    int b = slot >> 2;
    int h = g_topi[slot];
    int base = b*NH + h;

    float q = g_qb[slot*DH + e], k = g_kb[slot*DH + e], v = g_vb[slot*DH + e];
    float pq = q > 0.f ? q + 1.f : expf(q);   // elu(x)+1
    float pk = k > 0.f ? k + 1.f : expf(k);
    phiq_s[e] = pq; phik_s[e] = pk;
    float dcy = 1.f / (1.f + expf(-dlg[h*DH + e]));
    dec_s[e] = dcy;
    float Z = normalizer[base*DH + e];

    float r1 = pq * pk;              // -> phi_q . phi_k
    float r2 = pq * (Z + pk);        // -> den (pre-eps)
    #pragma unroll
    for (int o = 16; o > 0; o >>= 1) {
        r1 += __shfl_xor_sync(0xffffffffu, r1, o);
        r2 += __shfl_xor_sync(0xffffffffu, r2, o);
    }
    int lane = e & 31, wid = e >> 5;
    if (lane == 0) { partial[wid] = r1; partial[2 + wid] = r2; }
    __syncthreads();
    float pkdot = partial[0] + partial[1];
    float den   = partial[2] + partial[3] + 1e-6f;

    const float* Sg = matrix + (size_t)base*DH*DH;
    float num = 0.f;
    #pragma unroll 8
    for (int d = 0; d < 64; d++) {
        float s = Sg[d*64 + e];
        Ssm[d*64 + e] = s;
        num += phiq_s[d] * s;
    }
    num += pkdot * v;                 // phi_q . dS column e
    float out = num / den;

    float r3 = (out + q) * Ww[h*DH + e];
    #pragma unroll
    for (int o = 16; o > 0; o >>= 1) r3 += __shfl_xor_sync(0xffffffffu, r3, o);
    if (lane == 0) partial[4 + wid] = r3;
    __syncthreads();
    float wl = g_toplg[slot] + partial[4] + partial[5] + bw[h];
    float wprob = 1.f / (1.f + expf(-wl));

    out_norm[base*DH + e]  = Z*(1.f - wprob*dcy) + wprob*pk;
    g_outp[slot*DH + e]    = out * g_topp[slot];

    float wv = wprob * v;
    float* So = out_matrix + (size_t)base*DH*DH;
    #pragma unroll 8
    for (int d = 0; d < 64; d++) {
        So[d*64 + e] = Ssm[d*64 + e]*(1.f - wprob*dec_s[d]) + phik_s[d]*wv;
    }
}

// ---------------- K4: copy unselected slots ----------------------------------
__global__ __launch_bounds__(128) void k_copy(
    const float* __restrict__ matrix, const float* __restrict__ normalizer,
    float* __restrict__ out_matrix, float* __restrict__ out_norm)
{
    int s = blockIdx.x;
    if (g_mask[s]) return;
    const float4* src = (const float4*)(matrix + (size_t)s*4096);
    float4*       dst = (float4*)(out_matrix + (size_t)s*4096);
    #pragma unroll
    for (int i = threadIdx.x; i < 1024; i += 128) dst[i] = src[i];
    if (threadIdx.x < 64)
        out_norm[s*DH + threadIdx.x] = normalizer[s*DH + threadIdx.x];
}

// ---------------- K5: head-grouped output projection -> scratch --------------
// grid (8 m-chunks, 32 token-chunks, 16 heads), 256 threads. Tile 32 x 128.
__global__ __launch_bounds__(256) void k_outproj(const float* __restrict__ Wo)
{
    int h  = blockIdx.z;
    int n0 = blockIdx.y * 32;
    int m0 = blockIdx.x * 128;
    int cnt = g_counts[h];
    if (n0 >= cnt) return;

    __shared__ float Osm[32*65];
    __shared__ float Wsm[128*65];
    __shared__ int   ent_s[32];

    int tid = threadIdx.x;
    if (tid < 32) {
        int idx = n0 + tid;
        ent_s[tid] = g_list[h*NB + (idx < cnt ? idx : n0)];
    }
    __syncthreads();
    #pragma unroll
    for (int idx = tid; idx < 32*64; idx += 256) {
        int t = idx >> 6, ee = idx & 63;
        Osm[t*65 + ee] = g_outp[ent_s[t]*DH + ee];
    }
    const float* Wb = Wo + ((size_t)h*DM + m0)*DH;
    #pragma unroll
    for (int idx = tid; idx < 128*64; idx += 256) {
        int m = idx >> 6, ee = idx & 63;
        Wsm[m*65 + ee] = Wb[m*DH + ee];
    }
    __syncthreads();

    int tx = tid & 31, ty = tid >> 5;   // tx: 32 m-groups, ty: 8 t-groups
    float acc[4][4];
    #pragma unroll
    for (int i = 0; i < 4; i++)
        #pragma unroll
        for (int j = 0; j < 4; j++) acc[i][j] = 0.f;

    #pragma unroll 8
    for (int ee = 0; ee < 64; ee++) {
        float ov[4], wv[4];
        #pragma unroll
        for (int i = 0; i < 4; i++) ov[i] = Osm[(ty + 8*i)*65 + ee];
        #pragma unroll
        for (int j = 0; j < 4; j++) wv[j] = Wsm[(tx + 32*j)*65 + ee];
        #pragma unroll
        for (int i = 0; i < 4; i++)
            #pragma unroll
            for (int j = 0; j < 4; j++) acc[i][j] += ov[i]*wv[j];
    }
    #pragma unroll
    for (int i = 0; i < 4; i++) {
        int t = ty + 8*i;
        if (n0 + t < cnt) {
            int slot = ent_s[t];
            #pragma unroll
            for (int j = 0; j < 4; j++)
                g_scr[slot*DM + m0 + tx + 32*j] = acc[i][j];
        }
    }
}

// ---------------- K6: reduce scratch -> merged --------------------------------
__global__ __launch_bounds__(256) void k_merge(const float* __restrict__ bo,
                                               float* __restrict__ merged)
{
    int b = blockIdx.x;
    __shared__ int   hh[NA];
    __shared__ float pp[NA];
    if (threadIdx.x < NA) {
        hh[threadIdx.x] = g_topi[b*NA + threadIdx.x];
        pp[threadIdx.x] = g_topp[b*NA + threadIdx.x];
    }
    __syncthreads();
    for (int m = threadIdx.x; m < DM; m += 256) {
        float acc = 0.f;
        #pragma unroll
        for (int a = 0; a < NA; a++)
            acc += g_scr[(b*NA + a)*DM + m] + pp[a]*bo[hh[a]*DM + m];
        merged[b*DM + m] = acc;
    }
}

// ---------------- launch ------------------------------------------------------
extern "C" void kernel_launch(void* const* d_in, const int* in_sizes, int n_in,
                              void* d_out, int out_size) {
    const float* query      = (const float*)d_in[0];
    const float* key        = (const float*)d_in[1];
    const float* value      = (const float*)d_in[2];
    const float* matrix     = (const float*)d_in[3];
    const float* normalizer = (const float*)d_in[4];
    const float* Wq = (const float*)d_in[5];
    const float* bq = (const float*)d_in[6];
    const float* Wk = (const float*)d_in[7];
    const float* bk = (const float*)d_in[8];
    const float* Wv = (const float*)d_in[9];
    const float* bv = (const float*)d_in[10];
    const float* Wo = (const float*)d_in[11];
    const float* bo = (const float*)d_in[12];
    const float* We = (const float*)d_in[13];
    const float* be = (const float*)d_in[14];
    const float* Ww = (const float*)d_in[15];
    const float* bw = (const float*)d_in[16];
    const float* dl = (const float*)d_in[17];

    float* out        = (float*)d_out;
    float* merged     = out;                                // B*DM
    float* out_matrix = out + (size_t)NB*DM;                // B*H*64*64
    float* out_norm   = out_matrix + (size_t)NB*NH*DH*DH;   // B*H*64

    k_zero   <<<64, 256>>>();
    k_route  <<<NB, 128>>>(query, We, be);
    k_proj   <<<dim3(32, 16), 128>>>(query, key, value, Wq, bq, Wk, bk, Wv, bv);
    k_slot   <<<NSLOT, 64>>>(matrix, normalizer, Ww, bw, dl, out_matrix, out_norm);
    k_copy   <<<NB*NH, 128>>>(matrix, normalizer, out_matrix, out_norm);
    k_outproj<<<dim3(8, 32, 16), 256>>>(Wo);
    k_merge  <<<NB, 256>>>(bo, merged);
}

// round 3
// speedup vs baseline: 3.4395x; 3.4395x over previous
#include <cuda_runtime.h>
#include <math.h>

#define NB 1024
#define DM 1024
#define DH 64
#define NH 16
#define NA 4
#define NSLOT (NB*NA)

#define P_PROJ 6144          // 3 mats * 4 kchunks * 16 heads * 32 token-chunks
#define C1     10240         // copy slots handled in mega1
#define S_BLK  4096          // slot blocks in mega2

// ---------------- scratch (__device__ globals; no allocation allowed) --------
__device__ int           g_counts[NH];
__device__ int           g_list[NH*NB];        // packed (b<<2)|a  == slot id
__device__ unsigned char g_mask[NB*NH];        // 1 if slot (b,h) selected
__device__ int           g_topi[NSLOT];
__device__ float         g_topp[NSLOT];
__device__ float         g_toplg[NSLOT];
__device__ float         g_part[12*NSLOT*DH];  // (mat*4+kc) partial projections
__device__ float         g_outp[NSLOT*DH];     // out * top_p
__device__ float         g_scr[NSLOT*DM];      // merged contributions (16MB)

// ---------------- K0: zero counts + mask ------------------------------------
__global__ void k_zero() {
    int i = blockIdx.x * 256 + threadIdx.x;
    if (i < NH) g_counts[i] = 0;
    if (i < NB*NH) g_mask[i] = 0;
}

// ---------------- K1: routing (logits, softmax, top-4, head lists) ----------
__global__ __launch_bounds__(128) void k_route(const float* __restrict__ query,
                                               const float* __restrict__ We,
                                               const float* __restrict__ be) {
    __shared__ float qs[DM];
    __shared__ float lg[NH];
    int b = blockIdx.x;
    int tid = threadIdx.x;
    for (int i = tid; i < DM; i += 128) qs[i] = query[b*DM + i];
    __syncthreads();
    int w = tid >> 5, lane = tid & 31;
    #pragma unroll
    for (int hh = 0; hh < 4; hh++) {
        int h = w*4 + hh;
        const float* wr = We + h*DM;
        float s = 0.f;
        for (int m = lane; m < DM; m += 32) s += qs[m] * wr[m];
        #pragma unroll
        for (int o = 16; o > 0; o >>= 1) s += __shfl_xor_sync(0xffffffffu, s, o);
        if (lane == 0) lg[h] = s + be[h];
    }
    __syncthreads();
    if (tid == 0) {
        float l[NH], p[NH];
        float mx = -1e30f;
        #pragma unroll
        for (int h = 0; h < NH; h++) { l[h] = lg[h]; mx = fmaxf(mx, l[h]); }
        float se = 0.f;
        #pragma unroll
        for (int h = 0; h < NH; h++) { p[h] = expf(l[h] - mx); se += p[h]; }
        float inv = 1.f / se;
        #pragma unroll
        for (int h = 0; h < NH; h++) p[h] *= inv;
        bool used[NH];
        #pragma unroll
        for (int h = 0; h < NH; h++) used[h] = false;
        for (int a = 0; a < NA; a++) {
            int bi = -1; float bp = -1.f;
            for (int h = 0; h < NH; h++)
                if (!used[h] && p[h] > bp) { bp = p[h]; bi = h; }   // ties -> lowest idx
            used[bi] = true;
            int slot = b*NA + a;
            g_topi[slot]  = bi;
            g_topp[slot]  = bp;
            g_toplg[slot] = l[bi];
            g_mask[b*NH + bi] = 1;
            int pos = atomicAdd(&g_counts[bi], 1);
            g_list[bi*NB + pos] = (b << 2) | a;   // packed == slot id
        }
    }
}

// ---------------- copy of one unselected slot (128 threads) -----------------
__device__ __forceinline__ void copy_slot(int s,
    const float* __restrict__ matrix, const float* __restrict__ normalizer,
    float* __restrict__ out_matrix, float* __restrict__ out_norm)
{
    if (s >= NB*NH) return;
    if (g_mask[s]) return;
    const float4* src = (const float4*)(matrix + (size_t)s*4096);
    float4*       dst = (float4*)(out_matrix + (size_t)s*4096);
    #pragma unroll
    for (int i = threadIdx.x; i < 1024; i += 128) dst[i] = src[i];
    if (threadIdx.x < 64)
        out_norm[s*DH + threadIdx.x] = normalizer[s*DH + threadIdx.x];
}

// ---------------- mega1: K-split projections + copy slots [0,C1) -------------
// proj blocks: bid < P_PROJ. decomposition: mat(3) x kc(4) x head(16) x chunk(32).
// Tile: 32 tokens x 64 out, K-slice = 256 (4 sub-tiles of 64).
__global__ __launch_bounds__(128) void k_mega1(
    const float* __restrict__ query, const float* __restrict__ key,
    const float* __restrict__ value,
    const float* __restrict__ Wq, const float* __restrict__ Wk,
    const float* __restrict__ Wv,
    const float* __restrict__ matrix, const float* __restrict__ normalizer,
    float* __restrict__ out_matrix, float* __restrict__ out_norm)
{
    int bid = blockIdx.x;
    if (bid >= P_PROJ) {
        copy_slot(bid - P_PROJ, matrix, normalizer, out_matrix, out_norm);
        return;
    }
    __shared__ float Xs[32*65];
    __shared__ float Ws[64*65];
    __shared__ int   ent_s[32];

    int mat = bid >> 11;            // 0..2
    int r   = bid & 2047;
    int kc  = r >> 9;               // 0..3
    int r2  = r & 511;
    int h   = r2 >> 5;              // 0..15
    int chk = r2 & 31;              // 0..31
    int cnt = g_counts[h];
    int n0  = chk * 32;
    if (n0 >= cnt) return;

    int tid = threadIdx.x;
    if (tid < 32) {
        int idx = n0 + tid;
        ent_s[tid] = g_list[h*NB + (idx < cnt ? idx : n0)];
    }
    __syncthreads();

    const float* X = (mat == 0) ? query : (mat == 1 ? key : value);
    const float* W = ((mat == 0) ? Wq : (mat == 1 ? Wk : Wv))
                     + (size_t)h*DH*DM + kc*256;
    int k0 = kc * 256;

    int tx = tid & 15, ty = tid >> 4;      // tx: 16 d-groups, ty: 8 token-groups
    float acc[4][4];
    #pragma unroll
    for (int i = 0; i < 4; i++)
        #pragma unroll
        for (int j = 0; j < 4; j++) acc[i][j] = 0.f;

    for (int kt = 0; kt < 256; kt += 64) {
        #pragma unroll
        for (int idx = tid; idx < 32*64; idx += 128) {
            int t = idx >> 6, kk = idx & 63;
            Xs[t*65 + kk] = X[(ent_s[t] >> 2)*DM + k0 + kt + kk];
        }
        #pragma unroll
        for (int idx = tid; idx < 64*64; idx += 128) {
            int d = idx >> 6, kk = idx & 63;
            Ws[kk*65 + d] = W[d*DM + kt + kk];    // [kk][d], stride 65: CF
        }
        __syncthreads();
        #pragma unroll 8
        for (int kk = 0; kk < 64; kk++) {
            float xv[4], wv[4];
            #pragma unroll
            for (int i = 0; i < 4; i++) xv[i] = Xs[(ty + 8*i)*65 + kk];
            #pragma unroll
            for (int j = 0; j < 4; j++) wv[j] = Ws[kk*65 + tx + 16*j];
            #pragma unroll
            for (int i = 0; i < 4; i++)
                #pragma unroll
                for (int j = 0; j < 4; j++) acc[i][j] += xv[i]*wv[j];
        }
        __syncthreads();
    }
    size_t poff = (size_t)(mat*4 + kc) * (NSLOT*DH);
    #pragma unroll
    for (int i = 0; i < 4; i++) {
        int t = ty + 8*i;
        if (n0 + t < cnt) {
            int slot = ent_s[t];
            #pragma unroll
            for (int j = 0; j < 4; j++)
                g_part[poff + slot*DH + tx + 16*j] = acc[i][j];
        }
    }
}

// ---------------- mega2: slot update (128 thr) + copy slots [C1,16384) -------
__global__ __launch_bounds__(128) void k_mega2(
    const float* __restrict__ matrix, const float* __restrict__ normalizer,
    const float* __restrict__ bq, const float* __restrict__ bk,
    const float* __restrict__ bv,
    const float* __restrict__ Ww, const float* __restrict__ bw,
    const float* __restrict__ dlg,
    float* __restrict__ out_matrix, float* __restrict__ out_norm)
{
    if (blockIdx.x >= S_BLK) {
        copy_slot(C1 + blockIdx.x - S_BLK, matrix, normalizer, out_matrix, out_norm);
        return;
    }
    __shared__ float Ssm[64*64];
    __shared__ float phiq_s[64], phik_s[64], dec_s[64], wv_s[64];
    __shared__ float numh[128];
    __shared__ float red[6];
    __shared__ float s_wp;

    int slot = blockIdx.x;
    int tid = threadIdx.x;
    int e = tid & 63, half = tid >> 6;
    int b = slot >> 2;
    int h = g_topi[slot];
    int base = b*NH + h;
    const float* Sg = matrix + (size_t)base*DH*DH;

    float q = 0.f, v = 0.f, pk = 0.f, pq = 0.f, Z = 0.f, out = 0.f;
    if (half == 0) {
        q = bq[h*DH + e];
        float k = bk[h*DH + e];
        v = bv[h*DH + e];
        #pragma unroll
        for (int kc = 0; kc < 4; kc++) {
            q += g_part[(size_t)(0*4 + kc)*(NSLOT*DH) + slot*DH + e];
            k += g_part[(size_t)(1*4 + kc)*(NSLOT*DH) + slot*DH + e];
            v += g_part[(size_t)(2*4 + kc)*(NSLOT*DH) + slot*DH + e];
        }
        pq = q > 0.f ? q + 1.f : expf(q);     // elu+1
        pk = k > 0.f ? k + 1.f : expf(k);
        phiq_s[e] = pq; phik_s[e] = pk;
        dec_s[e] = 1.f / (1.f + expf(-dlg[h*DH + e]));
        Z = normalizer[base*DH + e];
        float r1 = pq * pk;
        float r2 = pq * (Z + pk);
        #pragma unroll
        for (int o = 16; o > 0; o >>= 1) {
            r1 += __shfl_xor_sync(0xffffffffu, r1, o);
            r2 += __shfl_xor_sync(0xffffffffu, r2, o);
        }
        int lane = e & 31, wid = e >> 5;
        if (lane == 0) { red[wid] = r1; red[2 + wid] = r2; }
    }
    __syncthreads();

    // both halves load S and accumulate partial num
    float nacc = 0.f;
    int d0 = half * 32;
    #pragma unroll 8
    for (int dd = 0; dd < 32; dd++) {
        int d = d0 + dd;
        float s = Sg[d*64 + e];
        Ssm[d*64 + e] = s;
        nacc += phiq_s[d] * s;
    }
    numh[tid] = nacc;
    __syncthreads();

    if (half == 0) {
        float pkdot = red[0] + red[1];
        float den   = red[2] + red[3] + 1e-6f;
        float num   = numh[e] + numh[64 + e] + pkdot * v;
        out = num / den;
        float r3 = (out + q) * Ww[h*DH + e];
        #pragma unroll
        for (int o = 16; o > 0; o >>= 1) r3 += __shfl_xor_sync(0xffffffffu, r3, o);
        int lane = e & 31, wid = e >> 5;
        if (lane == 0) red[4 + wid] = r3;
    }
    __syncthreads();

    if (half == 0) {
        float wl = g_toplg[slot] + red[4] + red[5] + bw[h];
        float wp = 1.f / (1.f + expf(-wl));
        out_norm[base*DH + e] = Z*(1.f - wp*dec_s[e]) + wp*pk;
        g_outp[slot*DH + e]   = out * g_topp[slot];
        wv_s[e] = wp * v;
        if (e == 0) s_wp = wp;
    }
    __syncthreads();

    float wp = s_wp;
    float wve = wv_s[e];
    float* So = out_matrix + (size_t)base*DH*DH;
    #pragma unroll 8
    for (int dd = 0; dd < 32; dd++) {
        int d = d0 + dd;
        So[d*64 + e] = Ssm[d*64 + e]*(1.f - wp*dec_s[d]) + phik_s[d]*wve;
    }
}

// ---------------- K5: head-grouped output projection -> scratch --------------
__global__ __launch_bounds__(256) void k_outproj(const float* __restrict__ Wo)
{
    int h  = blockIdx.z;
    int n0 = blockIdx.y * 32;
    int m0 = blockIdx.x * 128;
    int cnt = g_counts[h];
    if (n0 >= cnt) return;

    __shared__ float Osm[32*65];
    __shared__ float Wsm[128*65];
    __shared__ int   ent_s[32];

    int tid = threadIdx.x;
    if (tid < 32) {
        int idx = n0 + tid;
        ent_s[tid] = g_list[h*NB + (idx < cnt ? idx : n0)];
    }
    __syncthreads();
    #pragma unroll
    for (int idx = tid; idx < 32*64; idx += 256) {
        int t = idx >> 6, ee = idx & 63;
        Osm[t*65 + ee] = g_outp[ent_s[t]*DH + ee];
    }
    const float* Wb = Wo + ((size_t)h*DM + m0)*DH;
    #pragma unroll
    for (int idx = tid; idx < 128*64; idx += 256) {
        int m = idx >> 6, ee = idx & 63;
        Wsm[m*65 + ee] = Wb[m*DH + ee];
    }
    __syncthreads();

    int tx = tid & 31, ty = tid >> 5;
    float acc[4][4];
    #pragma unroll
    for (int i = 0; i < 4; i++)
        #pragma unroll
        for (int j = 0; j < 4; j++) acc[i][j] = 0.f;

    #pragma unroll 8
    for (int ee = 0; ee < 64; ee++) {
        float ov[4], wv[4];
        #pragma unroll
        for (int i = 0; i < 4; i++) ov[i] = Osm[(ty + 8*i)*65 + ee];
        #pragma unroll
        for (int j = 0; j < 4; j++) wv[j] = Wsm[(tx + 32*j)*65 + ee];
        #pragma unroll
        for (int i = 0; i < 4; i++)
            #pragma unroll
            for (int j = 0; j < 4; j++) acc[i][j] += ov[i]*wv[j];
    }
    #pragma unroll
    for (int i = 0; i < 4; i++) {
        int t = ty + 8*i;
        if (n0 + t < cnt) {
            int slot = ent_s[t];
            #pragma unroll
            for (int j = 0; j < 4; j++)
                g_scr[slot*DM + m0 + tx + 32*j] = acc[i][j];
        }
    }
}

// ---------------- K6: reduce scratch -> merged --------------------------------
__global__ __launch_bounds__(256) void k_merge(const float* __restrict__ bo,
                                               float* __restrict__ merged)
{
    int b = blockIdx.x;
    __shared__ int   hh[NA];
    __shared__ float pp[NA];
    if (threadIdx.x < NA) {
        hh[threadIdx.x] = g_topi[b*NA + threadIdx.x];
        pp[threadIdx.x] = g_topp[b*NA + threadIdx.x];
    }
    __syncthreads();
    for (int m = threadIdx.x; m < DM; m += 256) {
        float acc = 0.f;
        #pragma unroll
        for (int a = 0; a < NA; a++)
            acc += g_scr[(b*NA + a)*DM + m] + pp[a]*bo[hh[a]*DM + m];
        merged[b*DM + m] = acc;
    }
}

// ---------------- launch ------------------------------------------------------
extern "C" void kernel_launch(void* const* d_in, const int* in_sizes, int n_in,
                              void* d_out, int out_size) {
    const float* query      = (const float*)d_in[0];
    const float* key        = (const float*)d_in[1];
    const float* value      = (const float*)d_in[2];
    const float* matrix     = (const float*)d_in[3];
    const float* normalizer = (const float*)d_in[4];
    const float* Wq = (const float*)d_in[5];
    const float* bq = (const float*)d_in[6];
    const float* Wk = (const float*)d_in[7];
    const float* bk = (const float*)d_in[8];
    const float* Wv = (const float*)d_in[9];
    const float* bv = (const float*)d_in[10];
    const float* Wo = (const float*)d_in[11];
    const float* bo = (const float*)d_in[12];
    const float* We = (const float*)d_in[13];
    const float* be = (const float*)d_in[14];
    const float* Ww = (const float*)d_in[15];
    const float* bw = (const float*)d_in[16];
    const float* dl = (const float*)d_in[17];

    float* out        = (float*)d_out;
    float* merged     = out;                                // B*DM
    float* out_matrix = out + (size_t)NB*DM;                // B*H*64*64
    float* out_norm   = out_matrix + (size_t)NB*NH*DH*DH;   // B*H*64

    k_zero   <<<64, 256>>>();
    k_route  <<<NB, 128>>>(query, We, be);
    k_mega1  <<<P_PROJ + C1, 128>>>(query, key, value, Wq, Wk, Wv,
                                    matrix, normalizer, out_matrix, out_norm);
    k_mega2  <<<S_BLK + (NB*NH - C1), 128>>>(matrix, normalizer, bq, bk, bv,
                                             Ww, bw, dl, out_matrix, out_norm);
    k_outproj<<<dim3(8, 32, 16), 256>>>(Wo);
    k_merge  <<<NB, 256>>>(bo, merged);
}